// round 6
// baseline (speedup 1.0000x reference)
#include <cuda_runtime.h>
#include <cuda_bf16.h>
#include <cstdint>

#define HEADS 32
#define D 64
#define S 8192

#define CHUNKS 8
#define CH_S (S / CHUNKS)   // 1024
#define SUBS 64
#define B_NIT (CH_S / SUBS) // 16
#define C_ST 128
#define C_TPC 8             // s-tiles per CTA in kernel C

// ---------------- scratch ----------------
__device__ __align__(16) float g_part_ctx[HEADS * CHUNKS * D * D];   // 4 MiB
__device__ __align__(16) float g_part_rsum[HEADS * CHUNKS * D];
__device__ __align__(16) __nv_bfloat16 g_ctxT_hi[HEADS * D * D];     // [h][j][i]
__device__ __align__(16) __nv_bfloat16 g_ctxT_lo[HEADS * D * D];

// ---------------- helpers ----------------
__device__ __forceinline__ uint32_t smem_u32(const void* p) {
    uint32_t a;
    asm("{ .reg .u64 t; cvta.to.shared.u64 t, %1; cvt.u32.u64 %0, t; }" : "=r"(a) : "l"(p));
    return a;
}
#define SW(o) ((uint32_t)(o) ^ ((((uint32_t)(o)) >> 3) & 0x70))

__device__ __forceinline__ void ldmx4(uint32_t* r, uint32_t addr) {
    asm volatile("ldmatrix.sync.aligned.m8n8.x4.shared.b16 {%0,%1,%2,%3}, [%4];"
                 : "=r"(r[0]), "=r"(r[1]), "=r"(r[2]), "=r"(r[3]) : "r"(addr));
}
__device__ __forceinline__ void ldmx4t(uint32_t* r, uint32_t addr) {
    asm volatile("ldmatrix.sync.aligned.m8n8.x4.trans.shared.b16 {%0,%1,%2,%3}, [%4];"
                 : "=r"(r[0]), "=r"(r[1]), "=r"(r[2]), "=r"(r[3]) : "r"(addr));
}
__device__ __forceinline__ void mma16816(float* c, const uint32_t* a,
                                         uint32_t b0, uint32_t b1) {
    asm volatile(
        "mma.sync.aligned.m16n8k16.row.col.f32.bf16.bf16.f32 "
        "{%0,%1,%2,%3}, {%4,%5,%6,%7}, {%8,%9}, {%0,%1,%2,%3};"
        : "+f"(c[0]), "+f"(c[1]), "+f"(c[2]), "+f"(c[3])
        : "r"(a[0]), "r"(a[1]), "r"(a[2]), "r"(a[3]), "r"(b0), "r"(b1));
}
__device__ __forceinline__ uint32_t bf2(float x, float y) {
    uint32_t d;
    asm("cvt.rn.bf16x2.f32 %0, %1, %2;" : "=r"(d) : "f"(y), "f"(x));
    return d;
}
__device__ __forceinline__ void split4(float a, float b, float c, float d,
                                       uint2& hi, uint2& lo) {
    hi.x = bf2(a, b);
    hi.y = bf2(c, d);
    float ra = a - __uint_as_float(hi.x << 16);
    float rb = b - __uint_as_float(hi.x & 0xFFFF0000u);
    float rc = c - __uint_as_float(hi.y << 16);
    float rd = d - __uint_as_float(hi.y & 0xFFFF0000u);
    lo.x = bf2(ra, rb);
    lo.y = bf2(rc, rd);
}
__device__ __forceinline__ uint16_t bfu(float x) {
    __nv_bfloat16 h = __float2bfloat16_rn(x);
    return *(uint16_t*)&h;
}
__device__ __forceinline__ float bff(uint16_t u) {
    __nv_bfloat16 h = *(__nv_bfloat16*)&u;
    return __bfloat162float(h);
}

// =====================================================================
// Kernel B: per (head, chunk=1024s): part_ctx[i][j] = sum_s eK[i,s] V[j,s]
// Double-buffered smem tiles (Kh/Kl/Vh/Vl, 8KB each): buf b at b*32768.
// One __syncthreads per subtile; transform(t+1) overlaps MMA(t).
// =====================================================================
#define B_SRS 65536
__global__ void __launch_bounds__(256, 2) kernelB(const float* __restrict__ K,
                                                  const float* __restrict__ V) {
    extern __shared__ __align__(1024) char sm[];
    const uint32_t sb = smem_u32(sm);
    float* sRS = (float*)(sm + B_SRS);
    const int tid = threadIdx.x, lane = tid & 31, wid = tid >> 5;
    const int ch = blockIdx.x, h = blockIdx.y;

    if (tid < 64) sRS[tid] = 0.f;

    const size_t gbase = (size_t)h * D * S + (size_t)ch * CH_S;
    const int wm = wid & 3, wn = wid >> 2;
    const int lr = (lane & 7) + ((lane >> 3) & 1) * 8;
    const int lcs = lane >> 4;

    const float* kp[4];
    const float* vp[4];
    uint32_t so_[4];
    int rrow[4];
    #pragma unroll
    for (int u = 0; u < 4; u++) {
        const int idx = tid + (u << 8);
        const int r = idx >> 4, c4 = idx & 15;
        rrow[u] = r;
        so_[u] = SW(r * 128 + c4 * 8);
        kp[u] = K + gbase + (size_t)r * S + c4 * 4;
        vp[u] = V + gbase + (size_t)r * S + c4 * 4;
    }

    float4 pk[4], pv[4];
    #pragma unroll
    for (int u = 0; u < 4; u++) { pk[u] = *(const float4*)kp[u]; pv[u] = *(const float4*)vp[u]; }

    auto transform = [&](uint32_t bb) {
        #pragma unroll
        for (int u = 0; u < 4; u++) {
            float e0 = __expf(pk[u].x), e1 = __expf(pk[u].y);
            float e2 = __expf(pk[u].z), e3 = __expf(pk[u].w);
            float rsum = e0 + e1 + e2 + e3;
            rsum += __shfl_xor_sync(~0u, rsum, 1);
            rsum += __shfl_xor_sync(~0u, rsum, 2);
            rsum += __shfl_xor_sync(~0u, rsum, 4);
            rsum += __shfl_xor_sync(~0u, rsum, 8);
            if ((lane & 15) == 0) atomicAdd(&sRS[rrow[u]], rsum);
            uint2 hi, lo;
            split4(e0, e1, e2, e3, hi, lo);
            *(uint2*)(sm + bb + so_[u]) = hi;
            *(uint2*)(sm + bb + 8192 + so_[u]) = lo;
            split4(pv[u].x, pv[u].y, pv[u].z, pv[u].w, hi, lo);
            *(uint2*)(sm + bb + 16384 + so_[u]) = hi;
            *(uint2*)(sm + bb + 24576 + so_[u]) = lo;
        }
    };

    __syncthreads();            // sRS init visible before atomics
    transform(0);

    float acc[4][4] = {};

    for (int t = 0; t < B_NIT; t++) {
        __syncthreads();        // buf[t&1] filled; MMA(t-1) reads drained
        if (t + 1 < B_NIT) {
            const int off = (t + 1) * SUBS;
            #pragma unroll
            for (int u = 0; u < 4; u++) {
                pk[u] = *(const float4*)(kp[u] + off);
                pv[u] = *(const float4*)(vp[u] + off);
            }
        }
        const uint32_t bb = (uint32_t)(t & 1) * 32768;
        #pragma unroll
        for (int ks = 0; ks < 4; ks++) {
            const uint32_t aoff = SW((16 * wm + lr) * 128 + ks * 32 + lcs * 16);
            uint32_t ah[4], al[4];
            ldmx4(ah, sb + bb + aoff);
            ldmx4(al, sb + bb + 8192 + aoff);
            uint32_t bh[2][4], bl[2][4];
            #pragma unroll
            for (int hlf = 0; hlf < 2; hlf++) {
                const uint32_t boff =
                    SW((32 * wn + 16 * hlf + lr) * 128 + ks * 32 + lcs * 16);
                ldmx4(bh[hlf], sb + bb + 16384 + boff);
                ldmx4(bl[hlf], sb + bb + 24576 + boff);
            }
            #pragma unroll
            for (int nt = 0; nt < 4; nt++) {
                const int hf = nt >> 1, sub = nt & 1;
                const uint32_t bh0 = bh[hf][sub], bh1 = bh[hf][sub + 2];
                const uint32_t bl0 = bl[hf][sub], bl1 = bl[hf][sub + 2];
                mma16816(acc[nt], ah, bh0, bh1);
                mma16816(acc[nt], ah, bl0, bl1);
                mma16816(acc[nt], al, bh0, bh1);
            }
        }
        if (t + 1 < B_NIT) transform((uint32_t)((t + 1) & 1) * 32768);
    }
    __syncthreads();

    if (tid < 64) g_part_rsum[(h * CHUNKS + ch) * D + tid] = sRS[tid];

    float* pc = g_part_ctx + (size_t)(h * CHUNKS + ch) * (D * D);
    const int g8 = lane >> 2, tig = lane & 3;
    #pragma unroll
    for (int nt = 0; nt < 4; nt++) {
        const int j = 32 * wn + 8 * nt + 2 * tig;
        const int i0 = 16 * wm + g8;
        float2 v0 = {acc[nt][0], acc[nt][1]};
        float2 v1 = {acc[nt][2], acc[nt][3]};
        *(float2*)&pc[i0 * D + j] = v0;
        *(float2*)&pc[(i0 + 8) * D + j] = v1;
    }
}

// =====================================================================
// Kernel B2: reduce chunk partials, normalize rows, fold 1/8 scale,
// write transposed hi/lo bf16 ctx^T[j][i]
// =====================================================================
__global__ void __launch_bounds__(256) kernelB2() {
    const int h = blockIdx.x, tid = threadIdx.x;
    __shared__ float sinv[D];
    if (tid < D) {
        float s = 0.f;
        #pragma unroll
        for (int c = 0; c < CHUNKS; c++) s += g_part_rsum[(h * CHUNKS + c) * D + tid];
        sinv[tid] = 0.125f / s;
    }
    __syncthreads();
    for (int idx = tid; idx < D * D; idx += 256) {
        const int i = idx >> 6, j = idx & 63;
        float s = 0.f;
        #pragma unroll
        for (int c = 0; c < CHUNKS; c++)
            s += g_part_ctx[(size_t)(h * CHUNKS + c) * (D * D) + idx];
        const float val = s * sinv[i];
        const uint16_t hi = bfu(val);
        const uint16_t lo = bfu(val - bff(hi));
        g_ctxT_hi[h * D * D + j * D + i] = *(__nv_bfloat16*)&hi;
        g_ctxT_lo[h * D * D + j * D + i] = *(__nv_bfloat16*)&lo;
    }
}

// =====================================================================
// Kernel C: per (head, 8 s-tiles): out[j,s] = colinv[s]*sum_i ctxT[j,i]*EQ[i,s]
// smem: ctxh@0 ctxl@8K | EQ buf b @ 16K+b*32K (h half0/half1, l half0/half1)
//       | csum[8][128] @ 81920.  Double-buffered, one sync per tile.
// =====================================================================
#define C_EQ 16384
#define C_CS 81920
__global__ void __launch_bounds__(256, 2) kernelC(const float* __restrict__ Q,
                                                  float* __restrict__ O) {
    extern __shared__ __align__(1024) char sm[];
    const uint32_t sb = smem_u32(sm);
    const int tid = threadIdx.x, lane = tid & 31, wid = tid >> 5;
    const int stp = blockIdx.x, h = blockIdx.y;

    // zero all 8 colsum buffers (1024 floats)
    ((float4*)(sm + C_CS))[tid] = make_float4(0.f, 0.f, 0.f, 0.f);

    // ctx^T tiles
    {
        const uint64_t* srcH = (const uint64_t*)(g_ctxT_hi + h * D * D);
        const uint64_t* srcL = (const uint64_t*)(g_ctxT_lo + h * D * D);
        #pragma unroll
        for (int u = 0; u < 4; u++) {
            const int idx = tid + (u << 8);
            const uint32_t so = SW(idx * 8);
            *(uint64_t*)(sm + so) = srcH[idx];
            *(uint64_t*)(sm + 8192 + so) = srcL[idx];
        }
    }

    const size_t qbase = (size_t)h * D * S + (size_t)stp * (C_TPC * C_ST);
    const int s4 = tid & 31, iw = tid >> 5;
    const int tsel = s4 >> 4;
    const int srel = (s4 & 15) * 4;
    const float* qp[8];
    #pragma unroll
    for (int u = 0; u < 8; u++)
        qp[u] = Q + qbase + (size_t)(iw + 8 * u) * S + s4 * 4;

    float4 pq[8];
    #pragma unroll
    for (int u = 0; u < 8; u++) pq[u] = *(const float4*)qp[u];

    auto transform = [&](uint32_t eqb, float* csum) {
        float cs0 = 0.f, cs1 = 0.f, cs2 = 0.f, cs3 = 0.f;
        #pragma unroll
        for (int u = 0; u < 8; u++) {
            const int i = iw + 8 * u;
            float e0 = __expf(pq[u].x), e1 = __expf(pq[u].y);
            float e2 = __expf(pq[u].z), e3 = __expf(pq[u].w);
            cs0 += e0; cs1 += e1; cs2 += e2; cs3 += e3;
            uint2 hi, lo;
            split4(e0, e1, e2, e3, hi, lo);
            const uint32_t so = SW(i * 128 + srel * 2);
            *(uint2*)(sm + eqb + tsel * 8192 + so) = hi;
            *(uint2*)(sm + eqb + 16384 + tsel * 8192 + so) = lo;
        }
        atomicAdd(&csum[s4 * 4 + 0], cs0);
        atomicAdd(&csum[s4 * 4 + 1], cs1);
        atomicAdd(&csum[s4 * 4 + 2], cs2);
        atomicAdd(&csum[s4 * 4 + 3], cs3);
    };

    __syncthreads();            // csum init visible before atomics
    transform(C_EQ, (float*)(sm + C_CS));

    const int wm = wid & 3, wn = wid >> 2;
    const int lr = (lane & 7) + ((lane >> 3) & 1) * 8;
    const int lcs = lane >> 4;
    const int g8 = lane >> 2, tig = lane & 3;

    for (int t = 0; t < C_TPC; t++) {
        __syncthreads();        // EQ buf[t&1] + csum[t] ready; MMA(t-1) drained
        if (t + 1 < C_TPC) {
            #pragma unroll
            for (int u = 0; u < 8; u++)
                pq[u] = *(const float4*)(qp[u] + (t + 1) * C_ST);
        }
        const uint32_t eqb = C_EQ + (uint32_t)(t & 1) * 32768;
        float acc[8][4] = {};
        #pragma unroll
        for (int ks = 0; ks < 4; ks++) {
            const uint32_t aoff = SW((16 * wm + lr) * 128 + ks * 32 + lcs * 16);
            uint32_t ah[4], al[4];
            ldmx4(ah, sb + aoff);
            ldmx4(al, sb + 8192 + aoff);
            #pragma unroll
            for (int nb = 0; nb < 4; nb++) {
                const uint32_t boff = SW((ks * 16 + lr) * 128 + (nb * 16 + lcs * 8) * 2);
                uint32_t bh[4], bl[4];
                ldmx4t(bh, sb + eqb + wn * 8192 + boff);
                ldmx4t(bl, sb + eqb + 16384 + wn * 8192 + boff);
                float* a0 = acc[2 * nb];
                float* a1 = acc[2 * nb + 1];
                mma16816(a0, ah, bh[0], bh[1]);
                mma16816(a0, ah, bl[0], bl[1]);
                mma16816(a0, al, bh[0], bh[1]);
                mma16816(a1, ah, bh[2], bh[3]);
                mma16816(a1, ah, bl[2], bl[3]);
                mma16816(a1, al, bh[2], bh[3]);
            }
        }

        // epilogue: scale by 1/colsum(t), store
        const float* csum = (float*)(sm + C_CS) + t * 128;
        #pragma unroll
        for (int nt = 0; nt < 8; nt++) {
            const int sl = wn * 64 + nt * 8 + 2 * tig;
            const float2 cs = *(const float2*)&csum[sl];
            const float ix = __frcp_rn(cs.x), iy = __frcp_rn(cs.y);
            const int j = 16 * wm + g8;
            const size_t ob = ((size_t)h * D + j) * S
                            + (size_t)stp * (C_TPC * C_ST) + (size_t)t * C_ST + sl;
            float2 v0 = {acc[nt][0] * ix, acc[nt][1] * iy};
            float2 v1 = {acc[nt][2] * ix, acc[nt][3] * iy};
            *(float2*)(O + ob) = v0;
            *(float2*)(O + ob + 8 * S) = v1;
        }

        if (t + 1 < C_TPC)
            transform(C_EQ + (uint32_t)((t + 1) & 1) * 32768,
                      (float*)(sm + C_CS) + (t + 1) * 128);
    }
}

// =====================================================================
extern "C" void kernel_launch(void* const* d_in, const int* in_sizes, int n_in,
                              void* d_out, int out_size) {
    const float* q = (const float*)d_in[0];
    const float* k = (const float*)d_in[1];
    const float* v = (const float*)d_in[2];
    float* o = (float*)d_out;

    const int smemB = B_SRS + 256;        // 65792
    const int smemC = C_CS + 4096;        // 86016
    cudaFuncSetAttribute(kernelB, cudaFuncAttributeMaxDynamicSharedMemorySize, smemB);
    cudaFuncSetAttribute(kernelC, cudaFuncAttributeMaxDynamicSharedMemorySize, smemC);

    dim3 gridB(CHUNKS, HEADS);
    kernelB<<<gridB, 256, smemB>>>(k, v);
    kernelB2<<<HEADS, 256>>>();
    dim3 gridC(S / (C_TPC * C_ST), HEADS);
    kernelC<<<gridC, 256, smemC>>>(q, o);
}

// round 7
// speedup vs baseline: 1.0632x; 1.0632x over previous
#include <cuda_runtime.h>
#include <cuda_fp16.h>
#include <cstdint>

#define HEADS 32
#define D 64
#define S 8192

#define CHUNKS 8
#define CH_S (S / CHUNKS)   // 1024
#define SUBS 64
#define B_NIT (CH_S / SUBS) // 16
#define C_ST 128
#define C_TPC 8

// ---------------- scratch ----------------
__device__ __align__(16) float g_part_ctx[HEADS * CHUNKS * D * D];
__device__ __align__(16) float g_part_rsum[HEADS * CHUNKS * D];
__device__ __align__(16) __half g_ctxT[HEADS * D * D];   // [h][j][i], normalized+scaled

// ---------------- helpers ----------------
__device__ __forceinline__ uint32_t smem_u32(const void* p) {
    uint32_t a;
    asm("{ .reg .u64 t; cvta.to.shared.u64 t, %1; cvt.u32.u64 %0, t; }" : "=r"(a) : "l"(p));
    return a;
}
#define SW(o) ((uint32_t)(o) ^ ((((uint32_t)(o)) >> 3) & 0x70))

__device__ __forceinline__ void ldmx4(uint32_t* r, uint32_t addr) {
    asm volatile("ldmatrix.sync.aligned.m8n8.x4.shared.b16 {%0,%1,%2,%3}, [%4];"
                 : "=r"(r[0]), "=r"(r[1]), "=r"(r[2]), "=r"(r[3]) : "r"(addr));
}
__device__ __forceinline__ void ldmx4t(uint32_t* r, uint32_t addr) {
    asm volatile("ldmatrix.sync.aligned.m8n8.x4.trans.shared.b16 {%0,%1,%2,%3}, [%4];"
                 : "=r"(r[0]), "=r"(r[1]), "=r"(r[2]), "=r"(r[3]) : "r"(addr));
}
__device__ __forceinline__ void mma16816(float* c, const uint32_t* a,
                                         uint32_t b0, uint32_t b1) {
    asm volatile(
        "mma.sync.aligned.m16n8k16.row.col.f32.f16.f16.f32 "
        "{%0,%1,%2,%3}, {%4,%5,%6,%7}, {%8,%9}, {%0,%1,%2,%3};"
        : "+f"(c[0]), "+f"(c[1]), "+f"(c[2]), "+f"(c[3])
        : "r"(a[0]), "r"(a[1]), "r"(a[2]), "r"(a[3]), "r"(b0), "r"(b1));
}
// pack (x -> low half, y -> high half)
__device__ __forceinline__ uint32_t hf2(float x, float y) {
    uint32_t d;
    asm("cvt.rn.f16x2.f32 %0, %1, %2;" : "=r"(d) : "f"(y), "f"(x));
    return d;
}
__device__ __forceinline__ uint2 pack4(float a, float b, float c, float d) {
    uint2 r;
    r.x = hf2(a, b);
    r.y = hf2(c, d);
    return r;
}

// =====================================================================
// Kernel B: per (head, chunk=1024s): part_ctx[i][j] = sum_s eK[i,s] V[j,s]
// fp16 single-pass. smem: K buf0 @0, V buf0 @8K, K buf1 @16K, V buf1 @24K,
// sRS @32K. Double-buffered, reg-prefetch, one sync per subtile.
// =====================================================================
#define B_SRS 32768
__global__ void __launch_bounds__(256, 3) kernelB(const float* __restrict__ K,
                                                  const float* __restrict__ V) {
    extern __shared__ __align__(1024) char sm[];
    const uint32_t sb = smem_u32(sm);
    float* sRS = (float*)(sm + B_SRS);
    const int tid = threadIdx.x, lane = tid & 31, wid = tid >> 5;
    const int ch = blockIdx.x, h = blockIdx.y;

    if (tid < 64) sRS[tid] = 0.f;

    const size_t gbase = (size_t)h * D * S + (size_t)ch * CH_S;
    const int wm = wid & 3, wn = wid >> 2;
    const int lr = (lane & 7) + ((lane >> 3) & 1) * 8;
    const int lcs = lane >> 4;

    const float* kp[4];
    const float* vp[4];
    uint32_t so_[4];
    int rrow[4];
    #pragma unroll
    for (int u = 0; u < 4; u++) {
        const int idx = tid + (u << 8);
        const int r = idx >> 4, c4 = idx & 15;
        rrow[u] = r;
        so_[u] = SW(r * 128 + c4 * 8);
        kp[u] = K + gbase + (size_t)r * S + c4 * 4;
        vp[u] = V + gbase + (size_t)r * S + c4 * 4;
    }

    float4 pk[4], pv[4];
    #pragma unroll
    for (int u = 0; u < 4; u++) { pk[u] = *(const float4*)kp[u]; pv[u] = *(const float4*)vp[u]; }

    auto transform = [&](uint32_t bb) {
        #pragma unroll
        for (int u = 0; u < 4; u++) {
            float e0 = __expf(pk[u].x), e1 = __expf(pk[u].y);
            float e2 = __expf(pk[u].z), e3 = __expf(pk[u].w);
            float rsum = e0 + e1 + e2 + e3;
            rsum += __shfl_xor_sync(~0u, rsum, 1);
            rsum += __shfl_xor_sync(~0u, rsum, 2);
            rsum += __shfl_xor_sync(~0u, rsum, 4);
            rsum += __shfl_xor_sync(~0u, rsum, 8);
            if ((lane & 15) == 0) atomicAdd(&sRS[rrow[u]], rsum);
            *(uint2*)(sm + bb + so_[u]) = pack4(e0, e1, e2, e3);
            *(uint2*)(sm + bb + 8192 + so_[u]) = pack4(pv[u].x, pv[u].y, pv[u].z, pv[u].w);
        }
    };

    __syncthreads();            // sRS init visible before atomics
    transform(0);

    float acc[4][4] = {};

    for (int t = 0; t < B_NIT; t++) {
        __syncthreads();        // buf[t&1] filled; MMA(t-1) reads drained
        if (t + 1 < B_NIT) {
            const int off = (t + 1) * SUBS;
            #pragma unroll
            for (int u = 0; u < 4; u++) {
                pk[u] = *(const float4*)(kp[u] + off);
                pv[u] = *(const float4*)(vp[u] + off);
            }
        }
        const uint32_t bb = (uint32_t)(t & 1) * 16384;
        #pragma unroll
        for (int ks = 0; ks < 4; ks++) {
            const uint32_t aoff = SW((16 * wm + lr) * 128 + ks * 32 + lcs * 16);
            uint32_t ah[4];
            ldmx4(ah, sb + bb + aoff);
            uint32_t bh[2][4];
            #pragma unroll
            for (int hlf = 0; hlf < 2; hlf++) {
                const uint32_t boff =
                    SW((32 * wn + 16 * hlf + lr) * 128 + ks * 32 + lcs * 16);
                ldmx4(bh[hlf], sb + bb + 8192 + boff);
            }
            #pragma unroll
            for (int nt = 0; nt < 4; nt++) {
                const int hf = nt >> 1, sub = nt & 1;
                mma16816(acc[nt], ah, bh[hf][sub], bh[hf][sub + 2]);
            }
        }
        if (t + 1 < B_NIT) transform((uint32_t)((t + 1) & 1) * 16384);
    }
    __syncthreads();

    if (tid < 64) g_part_rsum[(h * CHUNKS + ch) * D + tid] = sRS[tid];

    float* pc = g_part_ctx + (size_t)(h * CHUNKS + ch) * (D * D);
    const int g8 = lane >> 2, tig = lane & 3;
    #pragma unroll
    for (int nt = 0; nt < 4; nt++) {
        const int j = 32 * wn + 8 * nt + 2 * tig;
        const int i0 = 16 * wm + g8;
        float2 v0 = {acc[nt][0], acc[nt][1]};
        float2 v1 = {acc[nt][2], acc[nt][3]};
        *(float2*)&pc[i0 * D + j] = v0;
        *(float2*)&pc[(i0 + 8) * D + j] = v1;
    }
}

// =====================================================================
// Kernel B2: reduce chunk partials, normalize rows, fold 1/8 scale,
// write transposed fp16 ctx^T[j][i]
// =====================================================================
__global__ void __launch_bounds__(256) kernelB2() {
    const int h = blockIdx.x, tid = threadIdx.x;
    __shared__ float sinv[D];
    if (tid < D) {
        float s = 0.f;
        #pragma unroll
        for (int c = 0; c < CHUNKS; c++) s += g_part_rsum[(h * CHUNKS + c) * D + tid];
        sinv[tid] = 0.125f / s;
    }
    __syncthreads();
    for (int idx = tid; idx < D * D; idx += 256) {
        const int i = idx >> 6, j = idx & 63;
        float s = 0.f;
        #pragma unroll
        for (int c = 0; c < CHUNKS; c++)
            s += g_part_ctx[(size_t)(h * CHUNKS + c) * (D * D) + idx];
        g_ctxT[h * D * D + j * D + i] = __float2half_rn(s * sinv[i]);
    }
}

// =====================================================================
// Kernel C: per (head, 8 s-tiles): out[j,s] = colinv[s]*sum_i ctxT[j,i]*EQ[i,s]
// fp16 single-pass. smem: ctx @0 (8K) | EQ buf b @ 8K+b*16K (two 8K halves)
//       | csum[8][128] @ 40960.  Double-buffered, one sync per tile.
// =====================================================================
#define C_EQ 8192
#define C_CS 40960
__global__ void __launch_bounds__(256, 3) kernelC(const float* __restrict__ Q,
                                                  float* __restrict__ O) {
    extern __shared__ __align__(1024) char sm[];
    const uint32_t sb = smem_u32(sm);
    const int tid = threadIdx.x, lane = tid & 31, wid = tid >> 5;
    const int stp = blockIdx.x, h = blockIdx.y;

    // zero all 8 colsum buffers (1024 floats)
    ((float4*)(sm + C_CS))[tid] = make_float4(0.f, 0.f, 0.f, 0.f);

    // ctx^T tile (64 x 64 fp16, swizzled copy)
    {
        const uint64_t* src = (const uint64_t*)(g_ctxT + h * D * D);
        #pragma unroll
        for (int u = 0; u < 4; u++) {
            const int idx = tid + (u << 8);
            *(uint64_t*)(sm + SW(idx * 8)) = src[idx];
        }
    }

    const size_t qbase = (size_t)h * D * S + (size_t)stp * (C_TPC * C_ST);
    const int s4 = tid & 31, iw = tid >> 5;
    const int tsel = s4 >> 4;
    const int srel = (s4 & 15) * 4;
    const float* qp[8];
    #pragma unroll
    for (int u = 0; u < 8; u++)
        qp[u] = Q + qbase + (size_t)(iw + 8 * u) * S + s4 * 4;

    float4 pq[8];
    #pragma unroll
    for (int u = 0; u < 8; u++) pq[u] = *(const float4*)qp[u];

    auto transform = [&](uint32_t eqb, float* csum) {
        float cs0 = 0.f, cs1 = 0.f, cs2 = 0.f, cs3 = 0.f;
        #pragma unroll
        for (int u = 0; u < 8; u++) {
            const int i = iw + 8 * u;
            float e0 = __expf(pq[u].x), e1 = __expf(pq[u].y);
            float e2 = __expf(pq[u].z), e3 = __expf(pq[u].w);
            cs0 += e0; cs1 += e1; cs2 += e2; cs3 += e3;
            *(uint2*)(sm + eqb + tsel * 8192 + SW(i * 128 + srel * 2)) =
                pack4(e0, e1, e2, e3);
        }
        atomicAdd(&csum[s4 * 4 + 0], cs0);
        atomicAdd(&csum[s4 * 4 + 1], cs1);
        atomicAdd(&csum[s4 * 4 + 2], cs2);
        atomicAdd(&csum[s4 * 4 + 3], cs3);
    };

    __syncthreads();            // csum init visible before atomics
    transform(C_EQ, (float*)(sm + C_CS));

    const int wm = wid & 3, wn = wid >> 2;
    const int lr = (lane & 7) + ((lane >> 3) & 1) * 8;
    const int lcs = lane >> 4;
    const int g8 = lane >> 2, tig = lane & 3;

    for (int t = 0; t < C_TPC; t++) {
        __syncthreads();        // EQ buf[t&1] + csum[t] ready; MMA(t-1) drained
        if (t + 1 < C_TPC) {
            #pragma unroll
            for (int u = 0; u < 8; u++)
                pq[u] = *(const float4*)(qp[u] + (t + 1) * C_ST);
        }
        const uint32_t eqb = C_EQ + (uint32_t)(t & 1) * 16384;
        float acc[8][4] = {};
        #pragma unroll
        for (int ks = 0; ks < 4; ks++) {
            const uint32_t aoff = SW((16 * wm + lr) * 128 + ks * 32 + lcs * 16);
            uint32_t ah[4];
            ldmx4(ah, sb + aoff);
            #pragma unroll
            for (int nb = 0; nb < 4; nb++) {
                const uint32_t boff = SW((ks * 16 + lr) * 128 + (nb * 16 + lcs * 8) * 2);
                uint32_t bh[4];
                ldmx4t(bh, sb + eqb + wn * 8192 + boff);
                mma16816(acc[2 * nb], ah, bh[0], bh[1]);
                mma16816(acc[2 * nb + 1], ah, bh[2], bh[3]);
            }
        }

        // epilogue: scale by 1/colsum(t), store
        const float* csum = (float*)(sm + C_CS) + t * 128;
        #pragma unroll
        for (int nt = 0; nt < 8; nt++) {
            const int sl = wn * 64 + nt * 8 + 2 * tig;
            const float2 cs = *(const float2*)&csum[sl];
            const float ix = __frcp_rn(cs.x), iy = __frcp_rn(cs.y);
            const int j = 16 * wm + g8;
            const size_t ob = ((size_t)h * D + j) * S
                            + (size_t)stp * (C_TPC * C_ST) + (size_t)t * C_ST + sl;
            float2 v0 = {acc[nt][0] * ix, acc[nt][1] * iy};
            float2 v1 = {acc[nt][2] * ix, acc[nt][3] * iy};
            *(float2*)(O + ob) = v0;
            *(float2*)(O + ob + 8 * S) = v1;
        }

        if (t + 1 < C_TPC)
            transform(C_EQ + (uint32_t)((t + 1) & 1) * 16384,
                      (float*)(sm + C_CS) + (t + 1) * 128);
    }
}

// =====================================================================
extern "C" void kernel_launch(void* const* d_in, const int* in_sizes, int n_in,
                              void* d_out, int out_size) {
    const float* q = (const float*)d_in[0];
    const float* k = (const float*)d_in[1];
    const float* v = (const float*)d_in[2];
    float* o = (float*)d_out;

    const int smemB = B_SRS + 256;        // 33024
    const int smemC = C_CS + 4096;        // 45056
    cudaFuncSetAttribute(kernelB, cudaFuncAttributeMaxDynamicSharedMemorySize, smemB);
    cudaFuncSetAttribute(kernelC, cudaFuncAttributeMaxDynamicSharedMemorySize, smemC);

    dim3 gridB(CHUNKS, HEADS);
    kernelB<<<gridB, 256, smemB>>>(k, v);
    kernelB2<<<HEADS, 256>>>();
    dim3 gridC(S / (C_TPC * C_ST), HEADS);
    kernelC<<<gridC, 256, smemC>>>(q, o);
}